// round 16
// baseline (speedup 1.0000x reference)
#include <cuda_runtime.h>
#include <cuda_bf16.h>
#include <cuda_fp16.h>
#include <math.h>

#define BB 2
#define TT 2048
#define CC 2048
#define HH 16
#define DD 128
#define C3 (3*CC)
#define BT (BB*TT)

// ---------------- device scratch ----------------
__device__ unsigned g_qkvh[(size_t)BT * (C3/2)];       // fp16 qkv (GEMM1 fused out)
__device__ unsigned g_xh[(size_t)BT * CC / 2];
__device__ unsigned g_xl[(size_t)BT * CC / 2];
__device__ unsigned g_ah[(size_t)BT * CC / 2];
__device__ unsigned g_al[(size_t)BT * CC / 2];
__device__ unsigned g_wqkvh[(size_t)(CC/2) * C3];
__device__ unsigned g_wqkvl[(size_t)(CC/2) * C3];
__device__ unsigned g_wouth[(size_t)(CC/2) * CC];
__device__ unsigned g_woutl[(size_t)(CC/2) * CC];
__device__ float g_cos[TT * 64];
__device__ float g_sin[TT * 64];
__device__ int   g_len[BB];

// ---------------- helpers ----------------
__device__ __forceinline__ unsigned smem_u32(const void* p) {
    return (unsigned)__cvta_generic_to_shared(p);
}
__device__ __forceinline__ void mma_bf16(float* d, const unsigned* a, const unsigned* b) {
    asm volatile(
        "mma.sync.aligned.m16n8k16.row.col.f32.bf16.bf16.f32 "
        "{%0,%1,%2,%3}, {%4,%5,%6,%7}, {%8,%9}, {%0,%1,%2,%3};"
        : "+f"(d[0]), "+f"(d[1]), "+f"(d[2]), "+f"(d[3])
        : "r"(a[0]), "r"(a[1]), "r"(a[2]), "r"(a[3]), "r"(b[0]), "r"(b[1]));
}
__device__ __forceinline__ void mma_f16(float* d, const unsigned* a, const unsigned* b) {
    asm volatile(
        "mma.sync.aligned.m16n8k16.row.col.f32.f16.f16.f32 "
        "{%0,%1,%2,%3}, {%4,%5,%6,%7}, {%8,%9}, {%0,%1,%2,%3};"
        : "+f"(d[0]), "+f"(d[1]), "+f"(d[2]), "+f"(d[3])
        : "r"(a[0]), "r"(a[1]), "r"(a[2]), "r"(a[3]), "r"(b[0]), "r"(b[1]));
}
__device__ __forceinline__ void ldsm_x4_trans(unsigned* d, unsigned addr) {
    asm volatile("ldmatrix.sync.aligned.m8n8.x4.trans.shared.b16 {%0,%1,%2,%3}, [%4];"
                 : "=r"(d[0]), "=r"(d[1]), "=r"(d[2]), "=r"(d[3]) : "r"(addr));
}
__device__ __forceinline__ unsigned pack_h2(float a, float b) {
    __half2 h = __floats2half2_rn(a, b);
    return *(unsigned*)&h;
}
__device__ __forceinline__ unsigned pack_hi(float v0, float v1, float &r0, float &r1) {
    __nv_bfloat16 h0 = __float2bfloat16(v0);
    __nv_bfloat16 h1 = __float2bfloat16(v1);
    r0 = v0 - __bfloat162float(h0);
    r1 = v1 - __bfloat162float(h1);
    unsigned u0 = __bfloat16_as_ushort(h0), u1 = __bfloat16_as_ushort(h1);
    return u0 | (u1 << 16);
}
__device__ __forceinline__ unsigned pack_bf(float v0, float v1) {
    unsigned u0 = __bfloat16_as_ushort(__float2bfloat16(v0));
    unsigned u1 = __bfloat16_as_ushort(__float2bfloat16(v1));
    return u0 | (u1 << 16);
}

// ================= merged prep kernel: splits + rope tables + lengths =============
#define NBLK_A 16384
#define NBLK_B 24576
#define NBLK_C 8192
#define NBLK_D 512
#define NBLK_E 2
#define NBLK_PREP (NBLK_A + NBLK_B + NBLK_C + NBLK_D + NBLK_E)

__device__ __forceinline__ void split_b_elem(const float* __restrict__ W,
                                             unsigned* dh, unsigned* dl,
                                             int N, size_t idx) {
    int n = (int)(idx % N);
    int k2 = (int)(idx / N);
    float v0 = W[(size_t)(2 * k2) * N + n];
    float v1 = W[(size_t)(2 * k2 + 1) * N + n];
    float l0, l1;
    dh[idx] = pack_hi(v0, v1, l0, l1);
    dl[idx] = pack_bf(l0, l1);
}

__global__ void prep_kernel(const float* __restrict__ x, const void* __restrict__ mask,
                            const float* __restrict__ Wqkv, const float* __restrict__ Wout) {
    __shared__ int ssum[256];
    unsigned bi = blockIdx.x;
    int tid = threadIdx.x;
    if (bi < NBLK_A) {
        size_t w = (size_t)bi * 256 + tid;
        float2 v = *(const float2*)&x[w * 2];
        float l0, l1;
        g_xh[w] = pack_hi(v.x, v.y, l0, l1);
        g_xl[w] = pack_bf(l0, l1);
    } else if (bi < NBLK_A + NBLK_B) {
        size_t idx = (size_t)(bi - NBLK_A) * 256 + tid;
        split_b_elem(Wqkv, g_wqkvh, g_wqkvl, C3, idx);
    } else if (bi < NBLK_A + NBLK_B + NBLK_C) {
        size_t idx = (size_t)(bi - NBLK_A - NBLK_B) * 256 + tid;
        split_b_elem(Wout, g_wouth, g_woutl, CC, idx);
    } else if (bi < NBLK_A + NBLK_B + NBLK_C + NBLK_D) {
        int idx = (int)(bi - NBLK_A - NBLK_B - NBLK_C) * 256 + tid;
        int t = idx >> 6, i = idx & 63;
        float invf = (float)(1.0 / pow(10000.0, (double)i / 64.0));
        float ang = (float)t * invf;
        double a = (double)ang;
        g_cos[idx] = (float)cos(a);
        g_sin[idx] = (float)sin(a);
    } else {
        int b = (int)(bi - NBLK_A - NBLK_B - NBLK_C - NBLK_D);
        unsigned int w0 = *(const unsigned int*)mask;
        int cnt = 0;
        if (w0 == 0x01010101u) {
            const unsigned char* m = (const unsigned char*)mask + (size_t)b * TT;
            for (int i = tid; i < TT; i += 256) cnt += (m[i] != 0);
        } else if (w0 == 0x3F800000u) {
            const float* m = (const float*)mask + (size_t)b * TT;
            for (int i = tid; i < TT; i += 256) cnt += (m[i] != 0.0f);
        } else {
            const int* m = (const int*)mask + (size_t)b * TT;
            for (int i = tid; i < TT; i += 256) cnt += (m[i] != 0);
        }
        ssum[tid] = cnt;
        __syncthreads();
        for (int s = 128; s > 0; s >>= 1) {
            if (tid < s) ssum[tid] += ssum[tid + s];
            __syncthreads();
        }
        if (tid == 0) g_len[b] = ssum[0];
    }
}

// ============ bf16x3 GEMM: 128x128 tile, 256 threads / 8 warps (2x4), 64x32/warp ===
#define KCB 32
#define ASTRW 20
#define BSTRW 136
#define ATILEW (128 * ASTRW)
#define BTILEW (16 * BSTRW)
#define GEMM_SMEM ((4 * ATILEW + 4 * BTILEW) * 4)   // 75776 B -> 2 CTAs/SM
#define STGSTR 132

__device__ __forceinline__ void gemm_load_chunk_bf(
    unsigned* Ah, unsigned* Al, unsigned* Bh, unsigned* Bl,
    const unsigned* __restrict__ Agh, const unsigned* __restrict__ Agl,
    const unsigned* __restrict__ Bgh, const unsigned* __restrict__ Bgl,
    int row0, int col0, int kc, int K, int N, int tid)
{
    const int Kw = K >> 1;
#pragma unroll
    for (int i = 0; i < 2; i++) {                    // A: 128 rows x 16 words
        int c = i * 256 + tid;
        int row = c >> 2, segw = (c & 3) << 2;
        size_t gsrc = (size_t)(row0 + row) * Kw + (kc >> 1) + segw;
        int dstw = row * ASTRW + segw;
        asm volatile("cp.async.cg.shared.global [%0], [%1], 16;"
                     :: "r"(smem_u32(Ah + dstw)), "l"(Agh + gsrc));
        asm volatile("cp.async.cg.shared.global [%0], [%1], 16;"
                     :: "r"(smem_u32(Al + dstw)), "l"(Agl + gsrc));
    }
#pragma unroll
    for (int i = 0; i < 2; i++) {                    // B: 16 k'-rows x 128 words
        int c = i * 256 + tid;
        int krow = c >> 5, segw = (c & 31) << 2;
        size_t gsrc = (size_t)((kc >> 1) + krow) * N + col0 + segw;
        int dstw = krow * BSTRW + segw;
        asm volatile("cp.async.cg.shared.global [%0], [%1], 16;"
                     :: "r"(smem_u32(Bh + dstw)), "l"(Bgh + gsrc));
        asm volatile("cp.async.cg.shared.global [%0], [%1], 16;"
                     :: "r"(smem_u32(Bl + dstw)), "l"(Bgl + gsrc));
    }
    asm volatile("cp.async.commit_group;");
}

// warp tile 64x32: acc[mi<4][ni<4][4]
__device__ __forceinline__ void gemm_mainloop(
    unsigned* smw, float acc[4][4][4],
    const unsigned* __restrict__ Agh, const unsigned* __restrict__ Agl,
    const unsigned* __restrict__ Bgh, const unsigned* __restrict__ Bgl,
    int row0, int col0, int K, int N,
    int tid, int wr, int wc, int gr, int tig)
{
    unsigned* Ah = smw;
    unsigned* Al = smw + 2 * ATILEW;
    unsigned* Bh = smw + 4 * ATILEW;
    unsigned* Bl = smw + 4 * ATILEW + 2 * BTILEW;

#pragma unroll
    for (int mi = 0; mi < 4; mi++)
#pragma unroll
        for (int ni = 0; ni < 4; ni++)
#pragma unroll
            for (int r = 0; r < 4; r++) acc[mi][ni][r] = 0.f;

    const int nc = K / KCB;
    gemm_load_chunk_bf(Ah, Al, Bh, Bl, Agh, Agl, Bgh, Bgl, row0, col0, 0, K, N, tid);

    for (int c = 0; c < nc; c++) {
        if (c + 1 < nc) {
            int nb = (c + 1) & 1;
            gemm_load_chunk_bf(Ah + nb * ATILEW, Al + nb * ATILEW,
                               Bh + nb * BTILEW, Bl + nb * BTILEW,
                               Agh, Agl, Bgh, Bgl, row0, col0, (c + 1) * KCB, K, N, tid);
            asm volatile("cp.async.wait_group 1;");
        } else {
            asm volatile("cp.async.wait_group 0;");
        }
        __syncthreads();

        const unsigned* ah = Ah + (c & 1) * ATILEW;
        const unsigned* al = Al + (c & 1) * ATILEW;
        const unsigned* bh = Bh + (c & 1) * BTILEW;
        const unsigned* bl = Bl + (c & 1) * BTILEW;

#pragma unroll
        for (int s = 0; s < 2; s++) {
            const int kw = s * 8;
            unsigned afh[4][4], afl[4][4], bfh[4][2], bfl[4][2];
#pragma unroll
            for (int mi = 0; mi < 4; mi++) {
                int m0 = wr * 64 + mi * 16;
                int w0 = (m0 + gr) * ASTRW + kw + tig;
                int w1 = (m0 + 8 + gr) * ASTRW + kw + tig;
                afh[mi][0] = ah[w0];     afh[mi][1] = ah[w1];
                afh[mi][2] = ah[w0 + 4]; afh[mi][3] = ah[w1 + 4];
                afl[mi][0] = al[w0];     afl[mi][1] = al[w1];
                afl[mi][2] = al[w0 + 4]; afl[mi][3] = al[w1 + 4];
            }
#pragma unroll
            for (int ni = 0; ni < 4; ni++) {
                int n0 = wc * 32 + ni * 8;
                int w0 = (kw + tig) * BSTRW + n0 + gr;
                int w1 = (kw + 4 + tig) * BSTRW + n0 + gr;
                bfh[ni][0] = bh[w0]; bfh[ni][1] = bh[w1];
                bfl[ni][0] = bl[w0]; bfl[ni][1] = bl[w1];
            }
#pragma unroll
            for (int mi = 0; mi < 4; mi++)
#pragma unroll
                for (int ni = 0; ni < 4; ni++)
                    mma_bf16(acc[mi][ni], afl[mi], bfh[ni]);   // lo*hi
#pragma unroll
            for (int mi = 0; mi < 4; mi++)
#pragma unroll
                for (int ni = 0; ni < 4; ni++)
                    mma_bf16(acc[mi][ni], afh[mi], bfl[ni]);   // hi*lo
#pragma unroll
            for (int mi = 0; mi < 4; mi++)
#pragma unroll
                for (int ni = 0; ni < 4; ni++)
                    mma_bf16(acc[mi][ni], afh[mi], bfh[ni]);   // hi*hi
        }
        __syncthreads();
    }
}

// ----- GEMM1: qkv = x @ Wqkv with fused RoPE(+scale)+fp16 epilogue -> g_qkvh -----
__global__ __launch_bounds__(256, 2) void gemm1_kernel(
    const unsigned* __restrict__ Agh, const unsigned* __restrict__ Agl,
    const unsigned* __restrict__ Bgh, const unsigned* __restrict__ Bgl,
    int M, int N, int K)
{
    extern __shared__ unsigned smw[];
    const int tid  = threadIdx.x;
    const int lane = tid & 31, warp = tid >> 5;
    const int wr = warp >> 2, wc = warp & 3;
    const int gr = lane >> 2, tig = lane & 3;
    const int row0 = blockIdx.y * 128, col0 = blockIdx.x * 128;

    const int bb = row0 / TT;
    const int len = g_len[bb];
    if ((row0 % TT) >= len) return;     // dead row-tile: outputs never read

    float acc[4][4][4];
    gemm_mainloop(smw, acc, Agh, Agl, Bgh, Bgl, row0, col0, K, N, tid, wr, wc, gr, tig);

    // stage fp32 tile in smem (mainloop buffers are dead now)
    float* stg = (float*)smw;
#pragma unroll
    for (int mi = 0; mi < 4; mi++) {
        int mr = wr * 64 + mi * 16;
#pragma unroll
        for (int ni = 0; ni < 4; ni++) {
            int n0 = wc * 32 + ni * 8 + 2 * tig;
            *(float2*)&stg[(mr + gr) * STGSTR + n0] =
                make_float2(acc[mi][ni][0], acc[mi][ni][1]);
            *(float2*)&stg[(mr + 8 + gr) * STGSTR + n0] =
                make_float2(acc[mi][ni][2], acc[mi][ni][3]);
        }
    }
    __syncthreads();

    const int sec = col0 / CC;             // 0=Q, 1=K, 2=V
    const int h = (col0 % CC) / DD;        // head
    const int jw = tid & 63;
    const int r4 = tid >> 6;               // 0..3
    const float scale = 0.08838834764831845f;

    for (int it = 0; it < 32; it++) {
        int r = r4 + it * 4;
        int t = (row0 % TT) + r;
        if (t >= len) continue;
        size_t whead = ((size_t)(bb * TT + t)) * (C3/2) + (size_t)sec * (CC/2) + (size_t)h * 64;
        float out0, out1;
        if (sec == 2) {
            float2 v = *(float2*)&stg[r * STGSTR + 2 * jw];
            out0 = v.x; out1 = v.y;
        } else if (jw < 32) {
            int cidx = 2 * jw;
            float2 x1 = *(float2*)&stg[r * STGSTR + cidx];
            float2 x2 = *(float2*)&stg[r * STGSTR + cidx + 64];
            float c0 = g_cos[t * 64 + cidx],     s0 = g_sin[t * 64 + cidx];
            float c1 = g_cos[t * 64 + cidx + 1], s1 = g_sin[t * 64 + cidx + 1];
            out0 = x1.x * c0 - x2.x * s0;
            out1 = x1.y * c1 - x2.y * s1;
            if (sec == 0) { out0 *= scale; out1 *= scale; }
        } else {
            int cidx = 2 * jw;
            int cc = cidx - 64;
            float2 x2 = *(float2*)&stg[r * STGSTR + cidx];
            float2 x1 = *(float2*)&stg[r * STGSTR + cc];
            float c0 = g_cos[t * 64 + cc],     s0 = g_sin[t * 64 + cc];
            float c1 = g_cos[t * 64 + cc + 1], s1 = g_sin[t * 64 + cc + 1];
            out0 = x2.x * c0 + x1.x * s0;
            out1 = x2.y * c1 + x1.y * s1;
            if (sec == 0) { out0 *= scale; out1 *= scale; }
        }
        g_qkvh[whead + jw] = pack_h2(out0, out1);
    }
}

// ----- GEMM2: out = attn @ Wout, fp32 epilogue; dead row-tiles -> zeros -----
__global__ __launch_bounds__(256, 2) void gemm2_kernel(
    const unsigned* __restrict__ Agh, const unsigned* __restrict__ Agl,
    const unsigned* __restrict__ Bgh, const unsigned* __restrict__ Bgl,
    float* __restrict__ C, int M, int N, int K)
{
    extern __shared__ unsigned smw[];
    const int tid  = threadIdx.x;
    const int lane = tid & 31, warp = tid >> 5;
    const int wr = warp >> 2, wc = warp & 3;
    const int gr = lane >> 2, tig = lane & 3;
    const int row0 = blockIdx.y * 128, col0 = blockIdx.x * 128;

    const int bb = row0 / TT;
    const int len = g_len[bb];
    if ((row0 % TT) >= len) {
#pragma unroll
        for (int mi = 0; mi < 4; mi++) {
            int m0 = row0 + wr * 64 + mi * 16;
#pragma unroll
            for (int ni = 0; ni < 4; ni++) {
                int n0 = col0 + wc * 32 + ni * 8 + 2 * tig;
                float* p0 = C + (size_t)(m0 + gr) * N + n0;
                float* p1 = C + (size_t)(m0 + 8 + gr) * N + n0;
                p0[0] = 0.f; p0[1] = 0.f;
                p1[0] = 0.f; p1[1] = 0.f;
            }
        }
        return;
    }

    float acc[4][4][4];
    gemm_mainloop(smw, acc, Agh, Agl, Bgh, Bgl, row0, col0, K, N, tid, wr, wc, gr, tig);

#pragma unroll
    for (int mi = 0; mi < 4; mi++) {
        int m0 = row0 + wr * 64 + mi * 16;
#pragma unroll
        for (int ni = 0; ni < 4; ni++) {
            int n0 = col0 + wc * 32 + ni * 8 + 2 * tig;
            float* p0 = C + (size_t)(m0 + gr) * N + n0;
            float* p1 = C + (size_t)(m0 + 8 + gr) * N + n0;
            p0[0] = acc[mi][ni][0]; p0[1] = acc[mi][ni][1];
            p1[0] = acc[mi][ni][2]; p1[1] = acc[mi][ni][3];
        }
    }
}

// ====== FA-2 attention, all-fp16 operands: BLK_M=128, 8 warps x (m16 x n64) ======
#define HSTR 68
#define SMW_Q 0
#define SMW_K (128 * HSTR)
#define SMW_V (SMW_K + 64 * HSTR)
#define ATT_SMEM_W (SMW_V + 64 * HSTR)
#define ATT_SMEM_BYTES (ATT_SMEM_W * 4)

__global__ __launch_bounds__(256, 1) void attn_kernel() {
    extern __shared__ unsigned smu[];
    unsigned* Qw = smu + SMW_Q;
    unsigned* Kw = smu + SMW_K;
    unsigned* Vw = smu + SMW_V;
    const unsigned vbase = smem_u32(smu + SMW_V);

    const int tid = threadIdx.x;
    const int lane = tid & 31, wid = tid >> 5;
    const int gr = lane >> 2, tig = lane & 3;
    const int m0 = wid * 16;
    const int bh = blockIdx.y;
    const int b = bh >> 4, h = bh & 15;
    const int qi = (int)gridDim.x - 1 - (int)blockIdx.x;   // heavy tiles first
    const int qbase = qi * 128;

    const int len = g_len[b];
    if (qbase >= len) return;

    const unsigned* Qg = g_qkvh + (size_t)b * TT * (C3/2) + (size_t)h * 64;
    const unsigned* Kg = Qg + (CC/2);
    const unsigned* Vg = Qg + 2 * (CC/2);

#pragma unroll
    for (int l = 0; l < 8; l++) {
        int chunk = l * 256 + tid;
        int row = chunk >> 4, c4 = (chunk & 15) << 2;
        asm volatile("cp.async.cg.shared.global [%0], [%1], 16;"
                     :: "r"(smem_u32(Qw + row * HSTR + c4)),
                        "l"(Qg + (size_t)(qbase + row) * (C3/2) + c4));
    }
    asm volatile("cp.async.commit_group;" ::: "memory");

    float mo0 = -INFINITY, mo1 = -INFINITY, lr0 = 0.f, lr1 = 0.f;
    float oacc[16][4];
#pragma unroll
    for (int ni = 0; ni < 16; ni++)
#pragma unroll
        for (int r = 0; r < 4; r++) oacc[ni][r] = 0.f;

    const int nkt = 2 * qi + 2;
    for (int kt = 0; kt < nkt; kt++) {
#pragma unroll
        for (int l = 0; l < 4; l++) {
            int chunk = l * 256 + tid;
            int row = chunk >> 4, c4 = (chunk & 15) << 2;
            size_t gofs = (size_t)(kt * 64 + row) * (C3/2) + c4;
            asm volatile("cp.async.cg.shared.global [%0], [%1], 16;"
                         :: "r"(smem_u32(Kw + row * HSTR + c4)), "l"(Kg + gofs));
            asm volatile("cp.async.cg.shared.global [%0], [%1], 16;"
                         :: "r"(smem_u32(Vw + row * HSTR + c4)), "l"(Vg + gofs));
        }
        asm volatile("cp.async.commit_group;" ::: "memory");
        asm volatile("cp.async.wait_group 0;" ::: "memory");
        __syncthreads();

        float sa[8][4];
#pragma unroll
        for (int ni = 0; ni < 8; ni++)
#pragma unroll
            for (int r = 0; r < 4; r++) sa[ni][r] = 0.f;

#pragma unroll
        for (int ks = 0; ks < 8; ks++) {
            const int k0 = ks * 8;
            unsigned a[4];
            a[0] = Qw[(m0 + gr)     * HSTR + k0 + tig];
            a[1] = Qw[(m0 + 8 + gr) * HSTR + k0 + tig];
            a[2] = Qw[(m0 + gr)     * HSTR + k0 + 4 + tig];
            a[3] = Qw[(m0 + 8 + gr) * HSTR + k0 + 4 + tig];
#pragma unroll
            for (int ni = 0; ni < 8; ni++) {
                unsigned bfr[2];
                bfr[0] = Kw[(ni * 8 + gr) * HSTR + k0 + tig];
                bfr[1] = Kw[(ni * 8 + gr) * HSTR + k0 + 4 + tig];
                mma_f16(sa[ni], a, bfr);
            }
        }

        if (kt >= 2 * qi) {
            int r0 = qbase + m0 + gr, r1 = r0 + 8;
#pragma unroll
            for (int ni = 0; ni < 8; ni++) {
                int c0 = kt * 64 + ni * 8 + 2 * tig;
                if (c0     > r0) sa[ni][0] = -INFINITY;
                if (c0 + 1 > r0) sa[ni][1] = -INFINITY;
                if (c0     > r1) sa[ni][2] = -INFINITY;
                if (c0 + 1 > r1) sa[ni][3] = -INFINITY;
            }
        }

        float mx0 = -INFINITY, mx1 = -INFINITY;
#pragma unroll
        for (int ni = 0; ni < 8; ni++) {
            mx0 = fmaxf(mx0, fmaxf(sa[ni][0], sa[ni][1]));
            mx1 = fmaxf(mx1, fmaxf(sa[ni][2], sa[ni][3]));
        }
        mx0 = fmaxf(mx0, __shfl_xor_sync(0xffffffffu, mx0, 1));
        mx0 = fmaxf(mx0, __shfl_xor_sync(0xffffffffu, mx0, 2));
        mx1 = fmaxf(mx1, __shfl_xor_sync(0xffffffffu, mx1, 1));
        mx1 = fmaxf(mx1, __shfl_xor_sync(0xffffffffu, mx1, 2));
        float mn0 = fmaxf(mo0, mx0), mn1 = fmaxf(mo1, mx1);
        float cf0 = (mo0 == -INFINITY) ? 0.f : __expf(mo0 - mn0);
        float cf1 = (mo1 == -INFINITY) ? 0.f : __expf(mo1 - mn1);

        unsigned ph[8][2];
        float s0 = 0.f, s1 = 0.f;
#pragma unroll
        for (int ni = 0; ni < 8; ni++) {
            float p0 = (sa[ni][0] == -INFINITY) ? 0.f : __expf(sa[ni][0] - mn0);
            float p1 = (sa[ni][1] == -INFINITY) ? 0.f : __expf(sa[ni][1] - mn0);
            float p2 = (sa[ni][2] == -INFINITY) ? 0.f : __expf(sa[ni][2] - mn1);
            float p3 = (sa[ni][3] == -INFINITY) ? 0.f : __expf(sa[ni][3] - mn1);
            s0 += p0 + p1; s1 += p2 + p3;
            ph[ni][0] = pack_h2(p0, p1);
            ph[ni][1] = pack_h2(p2, p3);
        }
        s0 += __shfl_xor_sync(0xffffffffu, s0, 1);
        s0 += __shfl_xor_sync(0xffffffffu, s0, 2);
        s1 += __shfl_xor_sync(0xffffffffu, s1, 1);
        s1 += __shfl_xor_sync(0xffffffffu, s1, 2);
        lr0 = lr0 * cf0 + s0; mo0 = mn0;
        lr1 = lr1 * cf1 + s1; mo1 = mn1;

#pragma unroll
        for (int ni = 0; ni < 16; ni++) {
            oacc[ni][0] *= cf0; oacc[ni][1] *= cf0;
            oacc[ni][2] *= cf1; oacc[ni][3] *= cf1;
        }

        unsigned pa[4][4];
#pragma unroll
        for (int j = 0; j < 4; j++) {
            pa[j][0] = ph[2 * j][0];
            pa[j][1] = ph[2 * j][1];
            pa[j][2] = ph[2 * j + 1][0];
            pa[j][3] = ph[2 * j + 1][1];
        }

#pragma unroll
        for (int jj = 0; jj < 2; jj++) {
            int vrow = 32 * jj + lane;
#pragma unroll
            for (int ni = 0; ni < 16; ni++) {
                unsigned d[4];
                ldsm_x4_trans(d, vbase + vrow * (HSTR * 4) + ni * 16);
                mma_f16(oacc[ni], pa[2 * jj],     d);
                mma_f16(oacc[ni], pa[2 * jj + 1], d + 2);
            }
        }
        __syncthreads();
    }

    // epilogue: normalize, zero padded rows, write bf16 hi/lo (A operand of out-GEMM)
    {
        int r0 = m0 + gr, r1 = m0 + 8 + gr;
        int t0 = qbase + r0, t1 = qbase + r1;
        float inv0 = (t0 < len) ? 1.0f / lr0 : 0.f;
        float inv1 = (t1 < len) ? 1.0f / lr1 : 0.f;
        size_t base0 = (((size_t)b * TT + t0) * CC + (size_t)h * DD) >> 1;
        size_t base1 = (((size_t)b * TT + t1) * CC + (size_t)h * DD) >> 1;
#pragma unroll
        for (int ni = 0; ni < 16; ni++) {
            int w = ni * 4 + tig;
            float o0 = oacc[ni][0] * inv0, o1 = oacc[ni][1] * inv0;
            float o2 = oacc[ni][2] * inv1, o3 = oacc[ni][3] * inv1;
            float l0, l1, l2, l3;
            g_ah[base0 + w] = pack_hi(o0, o1, l0, l1);
            g_al[base0 + w] = pack_bf(l0, l1);
            g_ah[base1 + w] = pack_hi(o2, o3, l2, l3);
            g_al[base1 + w] = pack_bf(l2, l3);
        }
    }
}

// ---------------- launch ----------------
extern "C" void kernel_launch(void* const* d_in, const int* in_sizes, int n_in,
                              void* d_out, int out_size) {
    const float* x    = (const float*)d_in[0];
    const void*  mask = d_in[1];
    const float* Wqkv = (const float*)d_in[2];
    const float* Wout = (const float*)d_in[3];
    float* out = (float*)d_out;

    unsigned *xh, *xl, *ah, *al, *wqh, *wql, *woh, *wol;
    cudaGetSymbolAddress((void**)&xh,  g_xh);
    cudaGetSymbolAddress((void**)&xl,  g_xl);
    cudaGetSymbolAddress((void**)&ah,  g_ah);
    cudaGetSymbolAddress((void**)&al,  g_al);
    cudaGetSymbolAddress((void**)&wqh, g_wqkvh);
    cudaGetSymbolAddress((void**)&wql, g_wqkvl);
    cudaGetSymbolAddress((void**)&woh, g_wouth);
    cudaGetSymbolAddress((void**)&wol, g_woutl);

    // merged prep: splits + rope tables + lengths (all independent)
    prep_kernel<<<NBLK_PREP, 256>>>(x, mask, Wqkv, Wout);

    cudaFuncSetAttribute(gemm1_kernel, cudaFuncAttributeMaxDynamicSharedMemorySize, GEMM_SMEM);
    cudaFuncSetAttribute(gemm2_kernel, cudaFuncAttributeMaxDynamicSharedMemorySize, GEMM_SMEM);

    // qkv(fp16, rotated, scaled) = RoPE(x @ Wqkv) — fused epilogue, dead tiles skipped
    gemm1_kernel<<<dim3(C3 / 128, BT / 128), 256, GEMM_SMEM>>>(
        xh, xl, wqh, wql, BT, C3, CC);

    // causal flash attention (all-fp16, warp-local softmax, dead q-tiles skipped)
    cudaFuncSetAttribute(attn_kernel, cudaFuncAttributeMaxDynamicSharedMemorySize, ATT_SMEM_BYTES);
    attn_kernel<<<dim3(TT / 128, BB * HH), 256, ATT_SMEM_BYTES>>>();

    // out = attn @ Wout  (bf16x3; dead row-tiles -> zeros)
    gemm2_kernel<<<dim3(CC / 128, BT / 128), 256, GEMM_SMEM>>>(
        ah, al, woh, wol, out, BT, CC, CC);
}

// round 17
// speedup vs baseline: 1.0449x; 1.0449x over previous
#include <cuda_runtime.h>
#include <cuda_bf16.h>
#include <cuda_fp16.h>
#include <math.h>

#define BB 2
#define TT 2048
#define CC 2048
#define HH 16
#define DD 128
#define C3 (3*CC)
#define BT (BB*TT)

// ---------------- device scratch ----------------
__device__ unsigned g_qkvh[(size_t)BT * (C3/2)];       // fp16 qkv (GEMM1 fused out)
__device__ unsigned g_xh[(size_t)BT * CC / 2];
__device__ unsigned g_xl[(size_t)BT * CC / 2];
__device__ unsigned g_ah[(size_t)BT * CC / 2];
__device__ unsigned g_al[(size_t)BT * CC / 2];
__device__ unsigned g_wqkvh[(size_t)(CC/2) * C3];
__device__ unsigned g_wqkvl[(size_t)(CC/2) * C3];
__device__ unsigned g_wouth[(size_t)(CC/2) * CC];
__device__ unsigned g_woutl[(size_t)(CC/2) * CC];
__device__ float g_cos[TT * 64];
__device__ float g_sin[TT * 64];
__device__ int   g_len[BB];

// ---------------- helpers ----------------
__device__ __forceinline__ unsigned smem_u32(const void* p) {
    return (unsigned)__cvta_generic_to_shared(p);
}
__device__ __forceinline__ void mma_bf16(float* d, const unsigned* a, const unsigned* b) {
    asm volatile(
        "mma.sync.aligned.m16n8k16.row.col.f32.bf16.bf16.f32 "
        "{%0,%1,%2,%3}, {%4,%5,%6,%7}, {%8,%9}, {%0,%1,%2,%3};"
        : "+f"(d[0]), "+f"(d[1]), "+f"(d[2]), "+f"(d[3])
        : "r"(a[0]), "r"(a[1]), "r"(a[2]), "r"(a[3]), "r"(b[0]), "r"(b[1]));
}
__device__ __forceinline__ void mma_f16(float* d, const unsigned* a, const unsigned* b) {
    asm volatile(
        "mma.sync.aligned.m16n8k16.row.col.f32.f16.f16.f32 "
        "{%0,%1,%2,%3}, {%4,%5,%6,%7}, {%8,%9}, {%0,%1,%2,%3};"
        : "+f"(d[0]), "+f"(d[1]), "+f"(d[2]), "+f"(d[3])
        : "r"(a[0]), "r"(a[1]), "r"(a[2]), "r"(a[3]), "r"(b[0]), "r"(b[1]));
}
__device__ __forceinline__ void ldsm_x4(unsigned* d, unsigned addr) {
    asm volatile("ldmatrix.sync.aligned.m8n8.x4.shared.b16 {%0,%1,%2,%3}, [%4];"
                 : "=r"(d[0]), "=r"(d[1]), "=r"(d[2]), "=r"(d[3]) : "r"(addr));
}
__device__ __forceinline__ void ldsm_x4_trans(unsigned* d, unsigned addr) {
    asm volatile("ldmatrix.sync.aligned.m8n8.x4.trans.shared.b16 {%0,%1,%2,%3}, [%4];"
                 : "=r"(d[0]), "=r"(d[1]), "=r"(d[2]), "=r"(d[3]) : "r"(addr));
}
__device__ __forceinline__ unsigned pack_h2(float a, float b) {
    __half2 h = __floats2half2_rn(a, b);
    return *(unsigned*)&h;
}
__device__ __forceinline__ unsigned pack_hi(float v0, float v1, float &r0, float &r1) {
    __nv_bfloat16 h0 = __float2bfloat16(v0);
    __nv_bfloat16 h1 = __float2bfloat16(v1);
    r0 = v0 - __bfloat162float(h0);
    r1 = v1 - __bfloat162float(h1);
    unsigned u0 = __bfloat16_as_ushort(h0), u1 = __bfloat16_as_ushort(h1);
    return u0 | (u1 << 16);
}
__device__ __forceinline__ unsigned pack_bf(float v0, float v1) {
    unsigned u0 = __bfloat16_as_ushort(__float2bfloat16(v0));
    unsigned u1 = __bfloat16_as_ushort(__float2bfloat16(v1));
    return u0 | (u1 << 16);
}

// ================= merged prep kernel (widened): splits + rope tables + lengths ====
#define NBLK_A 8192     // split x: BT*CC/2 words, 2 words/thread
#define NBLK_B 6144     // split Wqkv: (CC/2)*C3 words, 4 words/thread
#define NBLK_C 2048     // split Wout: (CC/2)*CC words, 4 words/thread
#define NBLK_D 512
#define NBLK_E 2
#define NBLK_PREP (NBLK_A + NBLK_B + NBLK_C + NBLK_D + NBLK_E)

__device__ __forceinline__ void split_b_quad(const float* __restrict__ W,
                                             unsigned* dh, unsigned* dl,
                                             int N, size_t qidx) {
    // qidx indexes groups of 4 words along n; word[k2][n] = (W[2k2][n], W[2k2+1][n])
    int nq = (int)(qidx % (N / 4));
    int k2 = (int)(qidx / (N / 4));
    int n0 = nq * 4;
    float4 r0 = *(const float4*)&W[(size_t)(2 * k2) * N + n0];
    float4 r1 = *(const float4*)&W[(size_t)(2 * k2 + 1) * N + n0];
    size_t o = (size_t)k2 * N + n0;
    float l0, l1;
    unsigned h[4], l[4];
    h[0] = pack_hi(r0.x, r1.x, l0, l1); l[0] = pack_bf(l0, l1);
    h[1] = pack_hi(r0.y, r1.y, l0, l1); l[1] = pack_bf(l0, l1);
    h[2] = pack_hi(r0.z, r1.z, l0, l1); l[2] = pack_bf(l0, l1);
    h[3] = pack_hi(r0.w, r1.w, l0, l1); l[3] = pack_bf(l0, l1);
    *(uint4*)&dh[o] = make_uint4(h[0], h[1], h[2], h[3]);
    *(uint4*)&dl[o] = make_uint4(l[0], l[1], l[2], l[3]);
}

__global__ void prep_kernel(const float* __restrict__ x, const void* __restrict__ mask,
                            const float* __restrict__ Wqkv, const float* __restrict__ Wout) {
    __shared__ int ssum[256];
    unsigned bi = blockIdx.x;
    int tid = threadIdx.x;
    if (bi < NBLK_A) {
        size_t w0 = ((size_t)bi * 256 + tid) * 2;
        float4 v = *(const float4*)&x[w0 * 2];
        float l0, l1;
        unsigned h0 = pack_hi(v.x, v.y, l0, l1);
        unsigned q0 = pack_bf(l0, l1);
        unsigned h1 = pack_hi(v.z, v.w, l0, l1);
        unsigned q1 = pack_bf(l0, l1);
        *(uint2*)&g_xh[w0] = make_uint2(h0, h1);
        *(uint2*)&g_xl[w0] = make_uint2(q0, q1);
    } else if (bi < NBLK_A + NBLK_B) {
        size_t q = (size_t)(bi - NBLK_A) * 256 + tid;
        split_b_quad(Wqkv, g_wqkvh, g_wqkvl, C3, q);
    } else if (bi < NBLK_A + NBLK_B + NBLK_C) {
        size_t q = (size_t)(bi - NBLK_A - NBLK_B) * 256 + tid;
        split_b_quad(Wout, g_wouth, g_woutl, CC, q);
    } else if (bi < NBLK_A + NBLK_B + NBLK_C + NBLK_D) {
        int idx = (int)(bi - NBLK_A - NBLK_B - NBLK_C) * 256 + tid;
        int t = idx >> 6, i = idx & 63;
        float invf = (float)(1.0 / pow(10000.0, (double)i / 64.0));
        float ang = (float)t * invf;
        double a = (double)ang;
        g_cos[idx] = (float)cos(a);
        g_sin[idx] = (float)sin(a);
    } else {
        int b = (int)(bi - NBLK_A - NBLK_B - NBLK_C - NBLK_D);
        unsigned int w0 = *(const unsigned int*)mask;
        int cnt = 0;
        if (w0 == 0x01010101u) {
            const unsigned char* m = (const unsigned char*)mask + (size_t)b * TT;
            for (int i = tid; i < TT; i += 256) cnt += (m[i] != 0);
        } else if (w0 == 0x3F800000u) {
            const float* m = (const float*)mask + (size_t)b * TT;
            for (int i = tid; i < TT; i += 256) cnt += (m[i] != 0.0f);
        } else {
            const int* m = (const int*)mask + (size_t)b * TT;
            for (int i = tid; i < TT; i += 256) cnt += (m[i] != 0);
        }
        ssum[tid] = cnt;
        __syncthreads();
        for (int s = 128; s > 0; s >>= 1) {
            if (tid < s) ssum[tid] += ssum[tid + s];
            __syncthreads();
        }
        if (tid == 0) g_len[b] = ssum[0];
    }
}

// ====== bf16x3 GEMM: 128x128 tile, 128 threads / 4 warps (2x2), 64x64/warp ======
// A-frags via ldmatrix.x4; single barrier per chunk.
#define KCB 32
#define ASTRW 20
#define BSTRW 136
#define ATILEW (128 * ASTRW)
#define BTILEW (16 * BSTRW)
#define GEMM_SMEM ((4 * ATILEW + 4 * BTILEW) * 4)   // 75776 B -> 2 CTAs/SM
#define STGSTR 132

__device__ __forceinline__ void gemm_load_chunk_bf(
    unsigned* Ah, unsigned* Al, unsigned* Bh, unsigned* Bl,
    const unsigned* __restrict__ Agh, const unsigned* __restrict__ Agl,
    const unsigned* __restrict__ Bgh, const unsigned* __restrict__ Bgl,
    int row0, int col0, int kc, int K, int N, int tid)
{
    const int Kw = K >> 1;
#pragma unroll
    for (int i = 0; i < 4; i++) {
        int c = i * 128 + tid;
        int row = c >> 2, segw = (c & 3) << 2;
        size_t gsrc = (size_t)(row0 + row) * Kw + (kc >> 1) + segw;
        int dstw = row * ASTRW + segw;
        asm volatile("cp.async.cg.shared.global [%0], [%1], 16;"
                     :: "r"(smem_u32(Ah + dstw)), "l"(Agh + gsrc));
        asm volatile("cp.async.cg.shared.global [%0], [%1], 16;"
                     :: "r"(smem_u32(Al + dstw)), "l"(Agl + gsrc));
    }
#pragma unroll
    for (int i = 0; i < 4; i++) {
        int c = i * 128 + tid;
        int krow = c >> 5, segw = (c & 31) << 2;
        size_t gsrc = (size_t)((kc >> 1) + krow) * N + col0 + segw;
        int dstw = krow * BSTRW + segw;
        asm volatile("cp.async.cg.shared.global [%0], [%1], 16;"
                     :: "r"(smem_u32(Bh + dstw)), "l"(Bgh + gsrc));
        asm volatile("cp.async.cg.shared.global [%0], [%1], 16;"
                     :: "r"(smem_u32(Bl + dstw)), "l"(Bgl + gsrc));
    }
    asm volatile("cp.async.commit_group;");
}

__device__ __forceinline__ void gemm_mainloop(
    unsigned* smw, float acc[4][8][4],
    const unsigned* __restrict__ Agh, const unsigned* __restrict__ Agl,
    const unsigned* __restrict__ Bgh, const unsigned* __restrict__ Bgl,
    int row0, int col0, int K, int N,
    int tid, int wr, int wc, int gr, int tig)
{
    unsigned* Ah = smw;
    unsigned* Al = smw + 2 * ATILEW;
    unsigned* Bh = smw + 4 * ATILEW;
    unsigned* Bl = smw + 4 * ATILEW + 2 * BTILEW;

    const int lane = tid & 31;
    const int lrow = lane & 15;
    const int lcolB = ((lane >> 4) & 1) * 16;    // byte offset within row

#pragma unroll
    for (int mi = 0; mi < 4; mi++)
#pragma unroll
        for (int ni = 0; ni < 8; ni++)
#pragma unroll
            for (int r = 0; r < 4; r++) acc[mi][ni][r] = 0.f;

    const int nc = K / KCB;
    gemm_load_chunk_bf(Ah, Al, Bh, Bl, Agh, Agl, Bgh, Bgl, row0, col0, 0, K, N, tid);

    for (int c = 0; c < nc; c++) {
        asm volatile("cp.async.wait_group 0;");
        __syncthreads();
        if (c + 1 < nc) {
            int nb = (c + 1) & 1;
            gemm_load_chunk_bf(Ah + nb * ATILEW, Al + nb * ATILEW,
                               Bh + nb * BTILEW, Bl + nb * BTILEW,
                               Agh, Agl, Bgh, Bgl, row0, col0, (c + 1) * KCB, K, N, tid);
        }

        const unsigned* ah = Ah + (c & 1) * ATILEW;
        const unsigned* al = Al + (c & 1) * ATILEW;
        const unsigned* bh = Bh + (c & 1) * BTILEW;
        const unsigned* bl = Bl + (c & 1) * BTILEW;
        const unsigned ahB = smem_u32(ah) + (wr * 64 + lrow) * (ASTRW * 4) + lcolB;
        const unsigned alB = smem_u32(al) + (wr * 64 + lrow) * (ASTRW * 4) + lcolB;

#pragma unroll
        for (int s = 0; s < 2; s++) {
            const int kw = s * 8;
            const unsigned kwB = s * 32;
            unsigned afh[4][4], afl[4][4], bfh[8][2], bfl[8][2];
#pragma unroll
            for (int mi = 0; mi < 4; mi++) {
                ldsm_x4(afh[mi], ahB + mi * (16 * ASTRW * 4) + kwB);
                ldsm_x4(afl[mi], alB + mi * (16 * ASTRW * 4) + kwB);
            }
#pragma unroll
            for (int ni = 0; ni < 8; ni++) {
                int n0 = wc * 64 + ni * 8;
                int w0 = (kw + tig) * BSTRW + n0 + gr;
                int w1 = (kw + 4 + tig) * BSTRW + n0 + gr;
                bfh[ni][0] = bh[w0]; bfh[ni][1] = bh[w1];
                bfl[ni][0] = bl[w0]; bfl[ni][1] = bl[w1];
            }
#pragma unroll
            for (int mi = 0; mi < 4; mi++)
#pragma unroll
                for (int ni = 0; ni < 8; ni++)
                    mma_bf16(acc[mi][ni], afl[mi], bfh[ni]);   // lo*hi
#pragma unroll
            for (int mi = 0; mi < 4; mi++)
#pragma unroll
                for (int ni = 0; ni < 8; ni++)
                    mma_bf16(acc[mi][ni], afh[mi], bfl[ni]);   // hi*lo
#pragma unroll
            for (int mi = 0; mi < 4; mi++)
#pragma unroll
                for (int ni = 0; ni < 8; ni++)
                    mma_bf16(acc[mi][ni], afh[mi], bfh[ni]);   // hi*hi
        }
    }
    __syncthreads();   // all warps done with smem before epilogue reuse
}

// ----- GEMM1: qkv = x @ Wqkv with fused RoPE(+scale)+fp16 epilogue -> g_qkvh -----
__global__ __launch_bounds__(128, 2) void gemm1_kernel(
    const unsigned* __restrict__ Agh, const unsigned* __restrict__ Agl,
    const unsigned* __restrict__ Bgh, const unsigned* __restrict__ Bgl,
    int M, int N, int K)
{
    extern __shared__ unsigned smw[];
    const int tid  = threadIdx.x;
    const int lane = tid & 31, warp = tid >> 5;
    const int wr = warp >> 1, wc = warp & 1;
    const int gr = lane >> 2, tig = lane & 3;
    const int row0 = blockIdx.y * 128, col0 = blockIdx.x * 128;

    const int bb = row0 / TT;
    const int len = g_len[bb];
    if ((row0 % TT) >= len) return;     // dead row-tile: outputs never read

    float acc[4][8][4];
    gemm_mainloop(smw, acc, Agh, Agl, Bgh, Bgl, row0, col0, K, N, tid, wr, wc, gr, tig);

    // stage fp32 tile in smem (mainloop buffers are dead now)
    float* stg = (float*)smw;
#pragma unroll
    for (int mi = 0; mi < 4; mi++) {
        int mr = wr * 64 + mi * 16;
#pragma unroll
        for (int ni = 0; ni < 8; ni++) {
            int n0 = wc * 64 + ni * 8 + 2 * tig;
            *(float2*)&stg[(mr + gr) * STGSTR + n0] =
                make_float2(acc[mi][ni][0], acc[mi][ni][1]);
            *(float2*)&stg[(mr + 8 + gr) * STGSTR + n0] =
                make_float2(acc[mi][ni][2], acc[mi][ni][3]);
        }
    }
    __syncthreads();

    const int sec = col0 / CC;             // 0=Q, 1=K, 2=V
    const int h = (col0 % CC) / DD;        // head
    const int jw = tid & 63;
    const int r2 = tid >> 6;
    const float scale = 0.08838834764831845f;

    for (int it = 0; it < 64; it++) {
        int r = r2 + it * 2;
        int t = (row0 % TT) + r;
        if (t >= len) continue;
        size_t whead = ((size_t)(bb * TT + t)) * (C3/2) + (size_t)sec * (CC/2) + (size_t)h * 64;
        float out0, out1;
        if (sec == 2) {
            float2 v = *(float2*)&stg[r * STGSTR + 2 * jw];
            out0 = v.x; out1 = v.y;
        } else if (jw < 32) {
            int cidx = 2 * jw;
            float2 x1 = *(float2*)&stg[r * STGSTR + cidx];
            float2 x2 = *(float2*)&stg[r * STGSTR + cidx + 64];
            float c0 = g_cos[t * 64 + cidx],     s0 = g_sin[t * 64 + cidx];
            float c1 = g_cos[t * 64 + cidx + 1], s1 = g_sin[t * 64 + cidx + 1];
            out0 = x1.x * c0 - x2.x * s0;
            out1 = x1.y * c1 - x2.y * s1;
            if (sec == 0) { out0 *= scale; out1 *= scale; }
        } else {
            int cidx = 2 * jw;
            int cc = cidx - 64;
            float2 x2 = *(float2*)&stg[r * STGSTR + cidx];
            float2 x1 = *(float2*)&stg[r * STGSTR + cc];
            float c0 = g_cos[t * 64 + cc],     s0 = g_sin[t * 64 + cc];
            float c1 = g_cos[t * 64 + cc + 1], s1 = g_sin[t * 64 + cc + 1];
            out0 = x2.x * c0 + x1.x * s0;
            out1 = x2.y * c1 + x1.y * s1;
            if (sec == 0) { out0 *= scale; out1 *= scale; }
        }
        g_qkvh[whead + jw] = pack_h2(out0, out1);
    }
}

// ----- GEMM2: out = attn @ Wout, fp32 epilogue; dead row-tiles -> zeros -----
__global__ __launch_bounds__(128, 2) void gemm2_kernel(
    const unsigned* __restrict__ Agh, const unsigned* __restrict__ Agl,
    const unsigned* __restrict__ Bgh, const unsigned* __restrict__ Bgl,
    float* __restrict__ C, int M, int N, int K)
{
    extern __shared__ unsigned smw[];
    const int tid  = threadIdx.x;
    const int lane = tid & 31, warp = tid >> 5;
    const int wr = warp >> 1, wc = warp & 1;
    const int gr = lane >> 2, tig = lane & 3;
    const int row0 = blockIdx.y * 128, col0 = blockIdx.x * 128;

    const int bb = row0 / TT;
    const int len = g_len[bb];
    if ((row0 % TT) >= len) {
#pragma unroll
        for (int mi = 0; mi < 4; mi++) {
            int m0 = row0 + wr * 64 + mi * 16;
#pragma unroll
            for (int ni = 0; ni < 8; ni++) {
                int n0 = col0 + wc * 64 + ni * 8 + 2 * tig;
                float* p0 = C + (size_t)(m0 + gr) * N + n0;
                float* p1 = C + (size_t)(m0 + 8 + gr) * N + n0;
                p0[0] = 0.f; p0[1] = 0.f;
                p1[0] = 0.f; p1[1] = 0.f;
            }
        }
        return;
    }

    float acc[4][8][4];
    gemm_mainloop(smw, acc, Agh, Agl, Bgh, Bgl, row0, col0, K, N, tid, wr, wc, gr, tig);

#pragma unroll
    for (int mi = 0; mi < 4; mi++) {
        int m0 = row0 + wr * 64 + mi * 16;
#pragma unroll
        for (int ni = 0; ni < 8; ni++) {
            int n0 = col0 + wc * 64 + ni * 8 + 2 * tig;
            float* p0 = C + (size_t)(m0 + gr) * N + n0;
            float* p1 = C + (size_t)(m0 + 8 + gr) * N + n0;
            p0[0] = acc[mi][ni][0]; p0[1] = acc[mi][ni][1];
            p1[0] = acc[mi][ni][2]; p1[1] = acc[mi][ni][3];
        }
    }
}

// ====== FA-2 attention, all-fp16 operands: BLK_M=128, 8 warps x (m16 x n64) ======
#define HSTR 68
#define SMW_Q 0
#define SMW_K (128 * HSTR)
#define SMW_V (SMW_K + 64 * HSTR)
#define ATT_SMEM_W (SMW_V + 64 * HSTR)
#define ATT_SMEM_BYTES (ATT_SMEM_W * 4)

__global__ __launch_bounds__(256, 1) void attn_kernel() {
    extern __shared__ unsigned smu[];
    unsigned* Qw = smu + SMW_Q;
    unsigned* Kw = smu + SMW_K;
    unsigned* Vw = smu + SMW_V;
    const unsigned vbase = smem_u32(smu + SMW_V);

    const int tid = threadIdx.x;
    const int lane = tid & 31, wid = tid >> 5;
    const int gr = lane >> 2, tig = lane & 3;
    const int m0 = wid * 16;
    const int bh = blockIdx.y;
    const int b = bh >> 4, h = bh & 15;
    const int qi = (int)gridDim.x - 1 - (int)blockIdx.x;   // heavy tiles first
    const int qbase = qi * 128;

    const int len = g_len[b];
    if (qbase >= len) return;

    const unsigned* Qg = g_qkvh + (size_t)b * TT * (C3/2) + (size_t)h * 64;
    const unsigned* Kg = Qg + (CC/2);
    const unsigned* Vg = Qg + 2 * (CC/2);

#pragma unroll
    for (int l = 0; l < 8; l++) {
        int chunk = l * 256 + tid;
        int row = chunk >> 4, c4 = (chunk & 15) << 2;
        asm volatile("cp.async.cg.shared.global [%0], [%1], 16;"
                     :: "r"(smem_u32(Qw + row * HSTR + c4)),
                        "l"(Qg + (size_t)(qbase + row) * (C3/2) + c4));
    }
    asm volatile("cp.async.commit_group;" ::: "memory");

    float mo0 = -INFINITY, mo1 = -INFINITY, lr0 = 0.f, lr1 = 0.f;
    float oacc[16][4];
#pragma unroll
    for (int ni = 0; ni < 16; ni++)
#pragma unroll
        for (int r = 0; r < 4; r++) oacc[ni][r] = 0.f;

    const int nkt = 2 * qi + 2;
    for (int kt = 0; kt < nkt; kt++) {
#pragma unroll
        for (int l = 0; l < 4; l++) {
            int chunk = l * 256 + tid;
            int row = chunk >> 4, c4 = (chunk & 15) << 2;
            size_t gofs = (size_t)(kt * 64 + row) * (C3/2) + c4;
            asm volatile("cp.async.cg.shared.global [%0], [%1], 16;"
                         :: "r"(smem_u32(Kw + row * HSTR + c4)), "l"(Kg + gofs));
            asm volatile("cp.async.cg.shared.global [%0], [%1], 16;"
                         :: "r"(smem_u32(Vw + row * HSTR + c4)), "l"(Vg + gofs));
        }
        asm volatile("cp.async.commit_group;" ::: "memory");
        asm volatile("cp.async.wait_group 0;" ::: "memory");
        __syncthreads();

        float sa[8][4];
#pragma unroll
        for (int ni = 0; ni < 8; ni++)
#pragma unroll
            for (int r = 0; r < 4; r++) sa[ni][r] = 0.f;

#pragma unroll
        for (int ks = 0; ks < 8; ks++) {
            const int k0 = ks * 8;
            unsigned a[4];
            a[0] = Qw[(m0 + gr)     * HSTR + k0 + tig];
            a[1] = Qw[(m0 + 8 + gr) * HSTR + k0 + tig];
            a[2] = Qw[(m0 + gr)     * HSTR + k0 + 4 + tig];
            a[3] = Qw[(m0 + 8 + gr) * HSTR + k0 + 4 + tig];
#pragma unroll
            for (int ni = 0; ni < 8; ni++) {
                unsigned bfr[2];
                bfr[0] = Kw[(ni * 8 + gr) * HSTR + k0 + tig];
                bfr[1] = Kw[(ni * 8 + gr) * HSTR + k0 + 4 + tig];
                mma_f16(sa[ni], a, bfr);
            }
        }

        if (kt >= 2 * qi) {
            int r0 = qbase + m0 + gr, r1 = r0 + 8;
#pragma unroll
            for (int ni = 0; ni < 8; ni++) {
                int c0 = kt * 64 + ni * 8 + 2 * tig;
                if (c0     > r0) sa[ni][0] = -INFINITY;
                if (c0 + 1 > r0) sa[ni][1] = -INFINITY;
                if (c0     > r1) sa[ni][2] = -INFINITY;
                if (c0 + 1 > r1) sa[ni][3] = -INFINITY;
            }
        }

        float mx0 = -INFINITY, mx1 = -INFINITY;
#pragma unroll
        for (int ni = 0; ni < 8; ni++) {
            mx0 = fmaxf(mx0, fmaxf(sa[ni][0], sa[ni][1]));
            mx1 = fmaxf(mx1, fmaxf(sa[ni][2], sa[ni][3]));
        }
        mx0 = fmaxf(mx0, __shfl_xor_sync(0xffffffffu, mx0, 1));
        mx0 = fmaxf(mx0, __shfl_xor_sync(0xffffffffu, mx0, 2));
        mx1 = fmaxf(mx1, __shfl_xor_sync(0xffffffffu, mx1, 1));
        mx1 = fmaxf(mx1, __shfl_xor_sync(0xffffffffu, mx1, 2));
        float mn0 = fmaxf(mo0, mx0), mn1 = fmaxf(mo1, mx1);
        float cf0 = (mo0 == -INFINITY) ? 0.f : __expf(mo0 - mn0);
        float cf1 = (mo1 == -INFINITY) ? 0.f : __expf(mo1 - mn1);

        unsigned ph[8][2];
        float s0 = 0.f, s1 = 0.f;
#pragma unroll
        for (int ni = 0; ni < 8; ni++) {
            float p0 = (sa[ni][0] == -INFINITY) ? 0.f : __expf(sa[ni][0] - mn0);
            float p1 = (sa[ni][1] == -INFINITY) ? 0.f : __expf(sa[ni][1] - mn0);
            float p2 = (sa[ni][2] == -INFINITY) ? 0.f : __expf(sa[ni][2] - mn1);
            float p3 = (sa[ni][3] == -INFINITY) ? 0.f : __expf(sa[ni][3] - mn1);
            s0 += p0 + p1; s1 += p2 + p3;
            ph[ni][0] = pack_h2(p0, p1);
            ph[ni][1] = pack_h2(p2, p3);
        }
        s0 += __shfl_xor_sync(0xffffffffu, s0, 1);
        s0 += __shfl_xor_sync(0xffffffffu, s0, 2);
        s1 += __shfl_xor_sync(0xffffffffu, s1, 1);
        s1 += __shfl_xor_sync(0xffffffffu, s1, 2);
        lr0 = lr0 * cf0 + s0; mo0 = mn0;
        lr1 = lr1 * cf1 + s1; mo1 = mn1;

#pragma unroll
        for (int ni = 0; ni < 16; ni++) {
            oacc[ni][0] *= cf0; oacc[ni][1] *= cf0;
            oacc[ni][2] *= cf1; oacc[ni][3] *= cf1;
        }

        unsigned pa[4][4];
#pragma unroll
        for (int j = 0; j < 4; j++) {
            pa[j][0] = ph[2 * j][0];
            pa[j][1] = ph[2 * j][1];
            pa[j][2] = ph[2 * j + 1][0];
            pa[j][3] = ph[2 * j + 1][1];
        }

#pragma unroll
        for (int jj = 0; jj < 2; jj++) {
            int vrow = 32 * jj + lane;
#pragma unroll
            for (int ni = 0; ni < 16; ni++) {
                unsigned d[4];
                ldsm_x4_trans(d, vbase + vrow * (HSTR * 4) + ni * 16);
                mma_f16(oacc[ni], pa[2 * jj],     d);
                mma_f16(oacc[ni], pa[2 * jj + 1], d + 2);
            }
        }
        __syncthreads();
    }

    // epilogue: normalize, zero padded rows, write bf16 hi/lo (A operand of out-GEMM)
    {
        int r0 = m0 + gr, r1 = m0 + 8 + gr;
        int t0 = qbase + r0, t1 = qbase + r1;
        float inv0 = (t0 < len) ? 1.0f / lr0 : 0.f;
        float inv1 = (t1 < len) ? 1.0f / lr1 : 0.f;
        size_t base0 = (((size_t)b * TT + t0) * CC + (size_t)h * DD) >> 1;
        size_t base1 = (((size_t)b * TT + t1) * CC + (size_t)h * DD) >> 1;
#pragma unroll
        for (int ni = 0; ni < 16; ni++) {
            int w = ni * 4 + tig;
            float o0 = oacc[ni][0] * inv0, o1 = oacc[ni][1] * inv0;
            float o2 = oacc[ni][2] * inv1, o3 = oacc[ni][3] * inv1;
            float l0, l1, l2, l3;
            g_ah[base0 + w] = pack_hi(o0, o1, l0, l1);
            g_al[base0 + w] = pack_bf(l0, l1);
            g_ah[base1 + w] = pack_hi(o2, o3, l2, l3);
            g_al[base1 + w] = pack_bf(l2, l3);
        }
    }
}

// ---------------- launch ----------------
extern "C" void kernel_launch(void* const* d_in, const int* in_sizes, int n_in,
                              void* d_out, int out_size) {
    const float* x    = (const float*)d_in[0];
    const void*  mask = d_in[1];
    const float* Wqkv = (const float*)d_in[2];
    const float* Wout = (const float*)d_in[3];
    float* out = (float*)d_out;

    unsigned *xh, *xl, *ah, *al, *wqh, *wql, *woh, *wol;
    cudaGetSymbolAddress((void**)&xh,  g_xh);
    cudaGetSymbolAddress((void**)&xl,  g_xl);
    cudaGetSymbolAddress((void**)&ah,  g_ah);
    cudaGetSymbolAddress((void**)&al,  g_al);
    cudaGetSymbolAddress((void**)&wqh, g_wqkvh);
    cudaGetSymbolAddress((void**)&wql, g_wqkvl);
    cudaGetSymbolAddress((void**)&woh, g_wouth);
    cudaGetSymbolAddress((void**)&wol, g_woutl);

    // merged prep: splits + rope tables + lengths (all independent)
    prep_kernel<<<NBLK_PREP, 256>>>(x, mask, Wqkv, Wout);

    cudaFuncSetAttribute(gemm1_kernel, cudaFuncAttributeMaxDynamicSharedMemorySize, GEMM_SMEM);
    cudaFuncSetAttribute(gemm2_kernel, cudaFuncAttributeMaxDynamicSharedMemorySize, GEMM_SMEM);

    // qkv(fp16, rotated, scaled) = RoPE(x @ Wqkv) — fused epilogue, dead tiles skipped
    gemm1_kernel<<<dim3(C3 / 128, BT / 128), 128, GEMM_SMEM>>>(
        xh, xl, wqh, wql, BT, C3, CC);

    // causal flash attention (all-fp16, warp-local softmax, dead q-tiles skipped)
    cudaFuncSetAttribute(attn_kernel, cudaFuncAttributeMaxDynamicSharedMemorySize, ATT_SMEM_BYTES);
    attn_kernel<<<dim3(TT / 128, BB * HH), 256, ATT_SMEM_BYTES>>>();

    // out = attn @ Wout  (bf16x3; dead row-tiles -> zeros)
    gemm2_kernel<<<dim3(CC / 128, BT / 128), 128, GEMM_SMEM>>>(
        ah, al, woh, wol, out, BT, CC, CC);
}